// round 14
// baseline (speedup 1.0000x reference)
#include <cuda_runtime.h>
#include <cuda_fp16.h>

#define MAXN 50000
#define MAXE 1250000
#define DD   64

// ---------------- scratch (static device globals; allocation-free) ----------------
__device__ int   g_is64;
__device__ unsigned long long g_pack[MAXN];        // [63:43) count, [43:0) sum(w) fixed 2^-20
__device__ float g_dis[MAXN];
__device__ int   g_cnt[MAXN];
__device__ int   g_ptr[MAXN];
__device__ int   g_bsum[64];
__device__ __align__(16) int2   g_csr[MAXE];       // .x = src row, .y = bits(norm)
__device__ __align__(16) __half g_h [MAXN * DD];   // h in fp16: 128B per node row
__device__ __align__(16) float  g_xa[MAXN * DD];
__device__ __align__(16) float  g_xb[MAXN * DD];

struct __align__(8) h4 { __half2 a, b; };          // 4 fp16 feats, 8B store/load unit

// packed f32x2 FMA (sm_103a): d = a*b + c lanewise on two fp32 packed in b64
#define FMA2(d, a, b, c) \
    asm("fma.rn.f32x2 %0, %1, %2, %3;" : "=l"(d) : "l"(a), "l"(b), "l"(c))
#define PACK2(out, x) \
    asm("mov.b64 %0, {%1, %2};" : "=l"(out) : "r"(__float_as_int(x)), "r"(__float_as_int(x)))
#define UNPACK2(lo, hi, in) \
    asm("mov.b64 {%0, %1}, %2;" : "=r"(lo), "=r"(hi) : "l"(in))

#define DEG_SCALE     1048576.0f          // 2^20
#define DEG_INV_SCALE (1.0f / 1048576.0f)
#define CNT_SHIFT     43
#define SUM_MASK      ((1ULL << 43) - 1ULL)

// ---------------- init + int64/int32 edge_index detection ----------------
// If edge_index is int64 (values < 2^31, nonneg), every odd int32 word is 0.
__global__ void init_kernel(const int* __restrict__ ei, int n) {
    int i = blockIdx.x * blockDim.x + threadIdx.x;
    if (i < n) { g_pack[i] = 0ULL; g_cnt[i] = 0; }
    if (i == 0) {
        bool is64 = true;
        for (int k = 0; k < 64; ++k)
            if (ei[2 * k + 1] != 0) { is64 = false; break; }
        g_is64 = is64 ? 1 : 0;
    }
}

// ---------------- degree histogram: ONE packed 64-bit atomic per edge ----------------
__global__ void deg_kernel(const int* __restrict__ ei, const float* __restrict__ w, int E) {
    int e = blockIdx.x * blockDim.x + threadIdx.x;
    if (e >= E) return;
    int c = g_is64 ? ei[2 * (E + e)] : ei[E + e];
    unsigned long long p = (1ULL << CNT_SHIFT)
                         + (unsigned long long)__float2ull_rn(w[e] * DEG_SCALE);
    atomicAdd(&g_pack[c], p);
}

// ---------------- scan pass 1 (block-local exclusive) + dis computation fused ----------------
__global__ void scan1_kernel(int n) {
    __shared__ int s[1024];
    int t = threadIdx.x;
    int i = blockIdx.x * 1024 + t;
    int v = 0;
    if (i < n) {
        unsigned long long p = g_pack[i];
        v = (int)(p >> CNT_SHIFT);
        float d = 2.0f + (float)(p & SUM_MASK) * DEG_INV_SCALE;   // improved=True self-loop
        g_dis[i] = (d > 0.0f) ? rsqrtf(d) : 0.0f;
    }
    s[t] = v;
    __syncthreads();
    for (int off = 1; off < 1024; off <<= 1) {
        int x = (t >= off) ? s[t - off] : 0;
        __syncthreads();
        s[t] += x;
        __syncthreads();
    }
    if (i < n) g_ptr[i] = s[t] - v;              // block-local exclusive
    if (t == 1023) g_bsum[blockIdx.x] = s[1023];
}

// ---------------- scan pass 2+3 fused: per-block recompute of bsum prefix ----------------
__global__ void scan3_kernel(int n, int nscan) {
    __shared__ int sv[64];
    int t = threadIdx.x;
    int blockNode = blockIdx.x << 8;             // this block covers nodes [b*256, b*256+256)
    int sb = blockNode >> 10;                    // owning scan1 block index
    if (t < 64) sv[t] = (t < sb && t < nscan) ? g_bsum[t] : 0;
    __syncthreads();
    if (t < 32) {
        int v = sv[t] + sv[t + 32];
#pragma unroll
        for (int o = 16; o > 0; o >>= 1) v += __shfl_down_sync(0xffffffffu, v, o);
        if (t == 0) sv[0] = v;
    }
    __syncthreads();
    int off = sv[0];
    int i = blockNode + t;
    if (i < n) { g_ptr[i] += off; g_cnt[i] = 0; }
}

__global__ void fill_kernel(const int* __restrict__ ei, const float* __restrict__ w, int E) {
    int e = blockIdx.x * blockDim.x + threadIdx.x;
    if (e >= E) return;
    int r, c;
    if (g_is64) { r = ei[2 * e]; c = ei[2 * (E + e)]; }
    else        { r = ei[e];     c = ei[E + e]; }
    float nm = g_dis[r] * w[e] * g_dis[c];
    int pos = g_ptr[c] + atomicAdd(&g_cnt[c], 1);
    g_csr[pos] = make_int2(r, __float_as_int(nm));
}

// ---------------- per-layer: H = X @ W (64x64), packed f32x2 FMA, fp16 epilogue ----------------
// 256 threads: 16 feature-groups (4 feats = 2 f32x2 lanes) x 16 pairs (2 nodes) = 32 nodes/block
__global__ void gemm_kernel(const float* __restrict__ X, const float* __restrict__ W,
                            __half* __restrict__ H, int n) {
    __shared__ float4 sW[64 * 16];     // W[k][j] as float4 groups over j
    __shared__ float  sx[32 * 64];     // 32 node rows
    int tid = threadIdx.x;
    const float4* W4 = (const float4*)W;
#pragma unroll
    for (int i = 0; i < 4; ++i) sW[tid + i * 256] = W4[tid + i * 256];
    int base = blockIdx.x * 32;
#pragma unroll
    for (int i = 0; i < 8; ++i) {
        int idx = tid + i * 256;
        int r = idx >> 6, k = idx & 63;
        int gn = base + r;
        sx[idx] = (gn < n) ? X[gn * 64 + k] : 0.0f;
    }
    __syncthreads();

    int pair = tid >> 4;          // 0..15 -> 2 nodes each
    int t    = tid & 15;          // feature group (4 feats = 2 packed lanes)
    int ln0  = pair * 2;
    unsigned long long a00 = 0ULL, a01 = 0ULL, a10 = 0ULL, a11 = 0ULL;
    const ulonglong2* sWp = (const ulonglong2*)sW;
#pragma unroll
    for (int k = 0; k < 64; ++k) {
        ulonglong2 wp = sWp[k * 16 + t];
        float xa = sx[ln0 * 64 + k];
        float xb = sx[ln0 * 64 + 64 + k];
        unsigned long long xaa, xbb;
        PACK2(xaa, xa);
        PACK2(xbb, xb);
        FMA2(a00, wp.x, xaa, a00);
        FMA2(a01, wp.y, xaa, a01);
        FMA2(a10, wp.x, xbb, a10);
        FMA2(a11, wp.y, xbb, a11);
    }
    h4* H2 = (h4*)H;
    int n0 = base + ln0;
    int f0, f1, f2, f3;
    if (n0 < n) {
        h4 p;
        UNPACK2(f0, f1, a00); UNPACK2(f2, f3, a01);
        p.a = __floats2half2_rn(__int_as_float(f0), __int_as_float(f1));
        p.b = __floats2half2_rn(__int_as_float(f2), __int_as_float(f3));
        H2[n0 * 16 + t] = p;
    }
    if (n0 + 1 < n) {
        h4 p;
        UNPACK2(f0, f1, a10); UNPACK2(f2, f3, a11);
        p.a = __floats2half2_rn(__int_as_float(f0), __int_as_float(f1));
        p.b = __floats2half2_rn(__int_as_float(f2), __int_as_float(f3));
        H2[(n0 + 1) * 16 + t] = p;
    }
}

// ---------------- aggregation: warp per node, half2 gather lanes, fp32 accumulate ----------------
// Software-pipelined: next iteration's edge int4 is prefetched while current gathers are in
// flight, removing the edge-load -> gather serial chain from the critical path.
template <int FUSE_FINAL>
__global__ void agg_kernel(const __half* __restrict__ H, float* __restrict__ Xo,
                           const float* __restrict__ bias,
                           const float* __restrict__ Wf, const float* __restrict__ bf,
                           float* __restrict__ out, int n) {
    int gid  = blockIdx.x * blockDim.x + threadIdx.x;
    int node = gid >> 5;
    int lane = gid & 31;
    if (node >= n) return;
    const __half2* hp = (const __half2*)H;

    float dsn = g_dis[node];
    float sn  = 2.0f * dsn * dsn;                // self-loop: dis*2.0*dis
    float2 hv = __half22float2(hp[node * 32 + lane]);
    float2 a0 = make_float2(hv.x * sn, hv.y * sn);
    float2 a1 = make_float2(0.0f, 0.0f);

    int s   = g_ptr[node];
    int end = s + g_cnt[node];
    int e   = s;
    if ((e & 1) && e < end) {                    // align to 16B boundary
        int2 e0 = g_csr[e];
        float2 h0 = __half22float2(hp[e0.x * 32 + lane]);
        float n0 = __int_as_float(e0.y);
        a0.x = fmaf(h0.x, n0, a0.x); a0.y = fmaf(h0.y, n0, a0.y);
        ++e;
    }
    int npairs = (end - e) >> 1;
    const int4* pb = (const int4*)g_csr + (e >> 1);
    if (npairs > 0) {
        int4 pr = pb[0];                         // prologue: first edge pair
        for (int i = 1; i < npairs; ++i) {
            int4 nx = pb[i];                     // prefetch next pair (independent)
            float2 h0 = __half22float2(hp[pr.x * 32 + lane]);
            float2 h1 = __half22float2(hp[pr.z * 32 + lane]);
            float n0 = __int_as_float(pr.y);
            float n1 = __int_as_float(pr.w);
            a0.x = fmaf(h0.x, n0, a0.x); a0.y = fmaf(h0.y, n0, a0.y);
            a1.x = fmaf(h1.x, n1, a1.x); a1.y = fmaf(h1.y, n1, a1.y);
            pr = nx;
        }
        {                                        // epilogue: last pair
            float2 h0 = __half22float2(hp[pr.x * 32 + lane]);
            float2 h1 = __half22float2(hp[pr.z * 32 + lane]);
            float n0 = __int_as_float(pr.y);
            float n1 = __int_as_float(pr.w);
            a0.x = fmaf(h0.x, n0, a0.x); a0.y = fmaf(h0.y, n0, a0.y);
            a1.x = fmaf(h1.x, n1, a1.x); a1.y = fmaf(h1.y, n1, a1.y);
        }
        e += npairs * 2;
    }
    if (e < end) {                               // odd trailing edge
        int2 e0 = g_csr[e];
        float2 h0 = __half22float2(hp[e0.x * 32 + lane]);
        float n0 = __int_as_float(e0.y);
        a0.x = fmaf(h0.x, n0, a0.x); a0.y = fmaf(h0.y, n0, a0.y);
    }
    float2 b2 = ((const float2*)bias)[lane];
    float2 r;
    r.x = fmaxf(a0.x + a1.x + b2.x, 0.0f);
    r.y = fmaxf(a0.y + a1.y + b2.y, 0.0f);
    if (FUSE_FINAL) {
        // final projection fused: out[node] = relu_row . Wf + bf
        float2 wv = ((const float2*)Wf)[lane];
        float sdot = r.x * wv.x + r.y * wv.y;
#pragma unroll
        for (int off = 16; off > 0; off >>= 1)
            sdot += __shfl_down_sync(0xffffffffu, sdot, off);
        if (lane == 0) out[node] = sdot + bf[0];
    } else {
        ((float2*)Xo)[node * 32 + lane] = r;
    }
}

// ---------------- launch ----------------
extern "C" void kernel_launch(void* const* d_in, const int* in_sizes, int n_in,
                              void* d_out, int out_size) {
    const float* x  = (const float*)d_in[0];
    const int*   ei = (const int*)d_in[1];
    const float* w  = (const float*)d_in[2];
    const float* Ws = (const float*)d_in[3];
    const float* bs = (const float*)d_in[4];
    const float* Wf = (const float*)d_in[5];
    const float* bf = (const float*)d_in[6];

    int n = in_sizes[0] / DD;
    int E = in_sizes[2];
    int L = in_sizes[3] / (DD * DD);

    float  *xa, *xb;
    __half *h;
    cudaGetSymbolAddress((void**)&xa, g_xa);
    cudaGetSymbolAddress((void**)&xb, g_xb);
    cudaGetSymbolAddress((void**)&h,  g_h);

    int nb256 = (n + 255) / 256;
    int eb256 = (E + 255) / 256;
    int nscan = (n + 1023) / 1024;

    init_kernel<<<nb256, 256>>>(ei, n);
    deg_kernel<<<eb256, 256>>>(ei, w, E);
    scan1_kernel<<<nscan, 1024>>>(n);
    scan3_kernel<<<nb256, 256>>>(n, nscan);
    fill_kernel<<<eb256, 256>>>(ei, w, E);

    const float* xin = x;
    float* bufs[2] = {xa, xb};
    for (int l = 0; l < L; ++l) {
        gemm_kernel<<<(n + 31) / 32, 256>>>(xin, Ws + (size_t)l * DD * DD, h, n);
        if (l == L - 1) {
            agg_kernel<1><<<(n * 32 + 255) / 256, 256>>>(h, nullptr, bs + (size_t)l * DD,
                                                         Wf, bf, (float*)d_out, n);
        } else {
            agg_kernel<0><<<(n * 32 + 255) / 256, 256>>>(h, bufs[l & 1], bs + (size_t)l * DD,
                                                         nullptr, nullptr, nullptr, n);
            xin = bufs[l & 1];
        }
    }
}

// round 15
// speedup vs baseline: 1.1339x; 1.1339x over previous
#include <cuda_runtime.h>
#include <cuda_fp16.h>

#define MAXN 50000
#define MAXE 1250000
#define DD   64

// ---------------- scratch (static device globals; allocation-free) ----------------
__device__ int   g_is64;
__device__ unsigned long long g_pack[MAXN];        // [63:43) count, [43:0) sum(w) fixed 2^-20
__device__ float g_dis[MAXN];
__device__ int   g_cnt[MAXN];
__device__ int   g_ptr[MAXN];
__device__ int   g_bsum[64];
__device__ __align__(16) int2   g_csr[MAXE];       // .x = src row, .y = half2(norm,norm) bits
__device__ __align__(16) __half g_h [MAXN * DD];   // h in fp16: 128B per node row
__device__ __align__(16) float  g_xa[MAXN * DD];
__device__ __align__(16) float  g_xb[MAXN * DD];

struct __align__(8) h4 { __half2 a, b; };          // 4 fp16 feats, 8B store/load unit

// packed f32x2 ops (sm_103a)
#define FMA2(d, a, b, c) \
    asm("fma.rn.f32x2 %0, %1, %2, %3;" : "=l"(d) : "l"(a), "l"(b), "l"(c))
#define PACK2(out, x) \
    asm("mov.b64 %0, {%1, %2};" : "=l"(out) : "r"(__float_as_int(x)), "r"(__float_as_int(x)))
#define UNPACK2(lo, hi, in) \
    asm("mov.b64 {%0, %1}, %2;" : "=r"(lo), "=r"(hi) : "l"(in))
#define ADDF2(d, a, b) \
    asm("add.rn.f32x2 %0, %1, %2;" : "=l"(d) : "l"(a), "l"(b))
#define PACKF2(out, lo, hi) \
    asm("mov.b64 %0, {%1, %2};" : "=l"(out) : "f"(lo), "f"(hi))

#define DEG_SCALE     1048576.0f          // 2^20
#define DEG_INV_SCALE (1.0f / 1048576.0f)
#define CNT_SHIFT     43
#define SUM_MASK      ((1ULL << 43) - 1ULL)

// ---------------- init + int64/int32 edge_index detection ----------------
__global__ void init_kernel(const int* __restrict__ ei, int n) {
    int i = blockIdx.x * blockDim.x + threadIdx.x;
    if (i < n) { g_pack[i] = 0ULL; g_cnt[i] = 0; }
    if (i == 0) {
        bool is64 = true;
        for (int k = 0; k < 64; ++k)
            if (ei[2 * k + 1] != 0) { is64 = false; break; }
        g_is64 = is64 ? 1 : 0;
    }
}

// ---------------- degree histogram: ONE packed 64-bit atomic per edge ----------------
__global__ void deg_kernel(const int* __restrict__ ei, const float* __restrict__ w, int E) {
    int e = blockIdx.x * blockDim.x + threadIdx.x;
    if (e >= E) return;
    int c = g_is64 ? ei[2 * (E + e)] : ei[E + e];
    unsigned long long p = (1ULL << CNT_SHIFT)
                         + (unsigned long long)__float2ull_rn(w[e] * DEG_SCALE);
    atomicAdd(&g_pack[c], p);
}

// ---------------- scan pass 1 (block-local exclusive) + dis computation fused ----------------
__global__ void scan1_kernel(int n) {
    __shared__ int s[1024];
    int t = threadIdx.x;
    int i = blockIdx.x * 1024 + t;
    int v = 0;
    if (i < n) {
        unsigned long long p = g_pack[i];
        v = (int)(p >> CNT_SHIFT);
        float d = 2.0f + (float)(p & SUM_MASK) * DEG_INV_SCALE;   // improved=True self-loop
        g_dis[i] = (d > 0.0f) ? rsqrtf(d) : 0.0f;
    }
    s[t] = v;
    __syncthreads();
    for (int off = 1; off < 1024; off <<= 1) {
        int x = (t >= off) ? s[t - off] : 0;
        __syncthreads();
        s[t] += x;
        __syncthreads();
    }
    if (i < n) g_ptr[i] = s[t] - v;              // block-local exclusive
    if (t == 1023) g_bsum[blockIdx.x] = s[1023];
}

// ---------------- scan pass 2+3 fused ----------------
__global__ void scan3_kernel(int n, int nscan) {
    __shared__ int sv[64];
    int t = threadIdx.x;
    int blockNode = blockIdx.x << 8;
    int sb = blockNode >> 10;
    if (t < 64) sv[t] = (t < sb && t < nscan) ? g_bsum[t] : 0;
    __syncthreads();
    if (t < 32) {
        int v = sv[t] + sv[t + 32];
#pragma unroll
        for (int o = 16; o > 0; o >>= 1) v += __shfl_down_sync(0xffffffffu, v, o);
        if (t == 0) sv[0] = v;
    }
    __syncthreads();
    int off = sv[0];
    int i = blockNode + t;
    if (i < n) { g_ptr[i] += off; g_cnt[i] = 0; }
}

// ---------------- CSR fill: norm stored as duplicated half2 ----------------
__global__ void fill_kernel(const int* __restrict__ ei, const float* __restrict__ w, int E) {
    int e = blockIdx.x * blockDim.x + threadIdx.x;
    if (e >= E) return;
    int r, c;
    if (g_is64) { r = ei[2 * e]; c = ei[2 * (E + e)]; }
    else        { r = ei[e];     c = ei[E + e]; }
    float nm = g_dis[r] * w[e] * g_dis[c];
    __half2 nh = __float2half2_rn(nm);
    int pos = g_ptr[c] + atomicAdd(&g_cnt[c], 1);
    g_csr[pos] = make_int2(r, *reinterpret_cast<int*>(&nh));
}

// ---------------- per-layer: H = X @ W (64x64), packed f32x2 FMA, fp16 epilogue ----------------
__global__ void gemm_kernel(const float* __restrict__ X, const float* __restrict__ W,
                            __half* __restrict__ H, int n) {
    __shared__ float4 sW[64 * 16];
    __shared__ float  sx[32 * 64];
    int tid = threadIdx.x;
    const float4* W4 = (const float4*)W;
#pragma unroll
    for (int i = 0; i < 4; ++i) sW[tid + i * 256] = W4[tid + i * 256];
    int base = blockIdx.x * 32;
#pragma unroll
    for (int i = 0; i < 8; ++i) {
        int idx = tid + i * 256;
        int r = idx >> 6, k = idx & 63;
        int gn = base + r;
        sx[idx] = (gn < n) ? X[gn * 64 + k] : 0.0f;
    }
    __syncthreads();

    int pair = tid >> 4;
    int t    = tid & 15;
    int ln0  = pair * 2;
    unsigned long long a00 = 0ULL, a01 = 0ULL, a10 = 0ULL, a11 = 0ULL;
    const ulonglong2* sWp = (const ulonglong2*)sW;
#pragma unroll
    for (int k = 0; k < 64; ++k) {
        ulonglong2 wp = sWp[k * 16 + t];
        float xa = sx[ln0 * 64 + k];
        float xb = sx[ln0 * 64 + 64 + k];
        unsigned long long xaa, xbb;
        PACK2(xaa, xa);
        PACK2(xbb, xb);
        FMA2(a00, wp.x, xaa, a00);
        FMA2(a01, wp.y, xaa, a01);
        FMA2(a10, wp.x, xbb, a10);
        FMA2(a11, wp.y, xbb, a11);
    }
    h4* H2 = (h4*)H;
    int n0 = base + ln0;
    int f0, f1, f2, f3;
    if (n0 < n) {
        h4 p;
        UNPACK2(f0, f1, a00); UNPACK2(f2, f3, a01);
        p.a = __floats2half2_rn(__int_as_float(f0), __int_as_float(f1));
        p.b = __floats2half2_rn(__int_as_float(f2), __int_as_float(f3));
        H2[n0 * 16 + t] = p;
    }
    if (n0 + 1 < n) {
        h4 p;
        UNPACK2(f0, f1, a10); UNPACK2(f2, f3, a11);
        p.a = __floats2half2_rn(__int_as_float(f0), __int_as_float(f1));
        p.b = __floats2half2_rn(__int_as_float(f2), __int_as_float(f3));
        H2[(n0 + 1) * 16 + t] = p;
    }
}

// ---------------- aggregation: warp per node; fp16 pair-products, f32x2 accumulate ----------------
// Per edge pair: HMUL2 + HFMA2 in fp16, one convert of the pair-sum, one packed f32 add.
template <int FUSE_FINAL>
__global__ void agg_kernel(const __half* __restrict__ H, float* __restrict__ Xo,
                           const float* __restrict__ bias,
                           const float* __restrict__ Wf, const float* __restrict__ bf,
                           float* __restrict__ out, int n) {
    int gid  = blockIdx.x * blockDim.x + threadIdx.x;
    int node = gid >> 5;
    int lane = gid & 31;
    if (node >= n) return;
    const __half2* hp = (const __half2*)H;

    float dsn = g_dis[node];
    float sn  = 2.0f * dsn * dsn;                // self-loop: dis*2.0*dis
    float2 hv = __half22float2(hp[node * 32 + lane]);
    unsigned long long acc;                      // packed f32x2 accumulator
    PACKF2(acc, hv.x * sn, hv.y * sn);

    int s   = g_ptr[node];
    int end = s + g_cnt[node];
    int e   = s;
    if ((e & 1) && e < end) {                    // align to 16B boundary
        int2 e0 = g_csr[e];
        __half2 nm = *reinterpret_cast<__half2*>(&e0.y);
        float2 p = __half22float2(__hmul2(hp[e0.x * 32 + lane], nm));
        unsigned long long pp;
        PACKF2(pp, p.x, p.y);
        ADDF2(acc, acc, pp);
        ++e;
    }
    const int4* csr2 = (const int4*)g_csr;
    for (; e + 1 < end; e += 2) {
        int4 pr = csr2[e >> 1];                  // two edges in one LDG.128
        __half2 nm0 = *reinterpret_cast<__half2*>(&pr.y);
        __half2 nm1 = *reinterpret_cast<__half2*>(&pr.w);
        __half2 ps = __hfma2(hp[pr.z * 32 + lane], nm1,
                             __hmul2(hp[pr.x * 32 + lane], nm0));   // fp16 pair-sum
        float2 pf = __half22float2(ps);
        unsigned long long pp;
        PACKF2(pp, pf.x, pf.y);
        ADDF2(acc, acc, pp);
    }
    if (e < end) {
        int2 e0 = g_csr[e];
        __half2 nm = *reinterpret_cast<__half2*>(&e0.y);
        float2 p = __half22float2(__hmul2(hp[e0.x * 32 + lane], nm));
        unsigned long long pp;
        PACKF2(pp, p.x, p.y);
        ADDF2(acc, acc, pp);
    }
    int ax, ay;
    UNPACK2(ax, ay, acc);
    float2 b2 = ((const float2*)bias)[lane];
    float2 r;
    r.x = fmaxf(__int_as_float(ax) + b2.x, 0.0f);
    r.y = fmaxf(__int_as_float(ay) + b2.y, 0.0f);
    if (FUSE_FINAL) {
        float2 wv = ((const float2*)Wf)[lane];
        float sdot = r.x * wv.x + r.y * wv.y;
#pragma unroll
        for (int off = 16; off > 0; off >>= 1)
            sdot += __shfl_down_sync(0xffffffffu, sdot, off);
        if (lane == 0) out[node] = sdot + bf[0];
    } else {
        ((float2*)Xo)[node * 32 + lane] = r;
    }
}

// ---------------- launch ----------------
extern "C" void kernel_launch(void* const* d_in, const int* in_sizes, int n_in,
                              void* d_out, int out_size) {
    const float* x  = (const float*)d_in[0];
    const int*   ei = (const int*)d_in[1];
    const float* w  = (const float*)d_in[2];
    const float* Ws = (const float*)d_in[3];
    const float* bs = (const float*)d_in[4];
    const float* Wf = (const float*)d_in[5];
    const float* bf = (const float*)d_in[6];

    int n = in_sizes[0] / DD;
    int E = in_sizes[2];
    int L = in_sizes[3] / (DD * DD);

    float  *xa, *xb;
    __half *h;
    cudaGetSymbolAddress((void**)&xa, g_xa);
    cudaGetSymbolAddress((void**)&xb, g_xb);
    cudaGetSymbolAddress((void**)&h,  g_h);

    int nb256 = (n + 255) / 256;
    int eb256 = (E + 255) / 256;
    int nscan = (n + 1023) / 1024;

    init_kernel<<<nb256, 256>>>(ei, n);
    deg_kernel<<<eb256, 256>>>(ei, w, E);
    scan1_kernel<<<nscan, 1024>>>(n);
    scan3_kernel<<<nb256, 256>>>(n, nscan);
    fill_kernel<<<eb256, 256>>>(ei, w, E);

    const float* xin = x;
    float* bufs[2] = {xa, xb};
    for (int l = 0; l < L; ++l) {
        gemm_kernel<<<(n + 31) / 32, 256>>>(xin, Ws + (size_t)l * DD * DD, h, n);
        if (l == L - 1) {
            agg_kernel<1><<<(n * 32 + 255) / 256, 256>>>(h, nullptr, bs + (size_t)l * DD,
                                                         Wf, bf, (float*)d_out, n);
        } else {
            agg_kernel<0><<<(n * 32 + 255) / 256, 256>>>(h, bufs[l & 1], bs + (size_t)l * DD,
                                                         nullptr, nullptr, nullptr, n);
            xin = bufs[l & 1];
        }
    }
}